// round 5
// baseline (speedup 1.0000x reference)
#include <cuda_runtime.h>
#include <cstdint>
#include <math.h>

#define HH 128
#define WW 128
#define HW 16384
#define CC 16
#define NPTS 32
#define NLINES (5 * HW)
#define LOI_FLOATS (NLINES * (CC * NPTS))   // 41,943,040
#define J_OFF LOI_FLOATS
#define S_OFF (LOI_FLOATS + 600)
#define TOPK 300
#define NSEG 128                             // prep blocks
#define SEGSZ 128
#define MAXCAND 4096

// ---- device scratch ----
__device__ float4 g_ft4[HW * 4];             // features (H,W,C)
__device__ float4 g_geom[NLINES];            // per-line (ux,uy,vx,vy)
__device__ unsigned long long g_keys[NSEG * SEGSZ];
__device__ int g_bcnt[NSEG];

// ---- packed f32x2 helpers ----
__device__ __forceinline__ unsigned long long pk2(float lo, float hi) {
    unsigned long long r;
    asm("mov.b64 %0, {%1, %2};" : "=l"(r) : "f"(lo), "f"(hi));
    return r;
}
__device__ __forceinline__ unsigned long long mul2(unsigned long long a, unsigned long long b) {
    unsigned long long d;
    asm("mul.rn.f32x2 %0, %1, %2;" : "=l"(d) : "l"(a), "l"(b));
    return d;
}
__device__ __forceinline__ unsigned long long fma2(unsigned long long a, unsigned long long b,
                                                   unsigned long long c) {
    unsigned long long d;
    asm("fma.rn.f32x2 %0, %1, %2, %3;" : "=l"(d) : "l"(a), "l"(b), "l"(c));
    return d;
}
__device__ __forceinline__ float2 up2(unsigned long long v) {
    float2 r;
    asm("mov.b64 {%0, %1}, %2;" : "=f"(r.x), "=f"(r.y) : "l"(v));
    return r;
}

// ---------------------------------------------------------------------------
// Kernel 1 (prep): transpose + geometry (trig once per pixel) + NMS compact.
// 128 blocks x 128 threads (fills more SMs than 64x256).
// ---------------------------------------------------------------------------
__global__ void __launch_bounds__(128) prep_kernel(
    const float* __restrict__ f,
    const float* __restrict__ md,
    const float* __restrict__ dis,
    const float* __restrict__ res,
    const float* __restrict__ jloc)
{
    __shared__ int s_cnt;
    const int tid = threadIdx.x;
    const int p = blockIdx.x * 128 + tid;
    if (tid == 0) s_cnt = 0;
    __syncthreads();

    const int yi = p >> 7;
    const int xi = p & 127;

#pragma unroll
    for (int j = 0; j < 4; j++) {
        float4 v;
        v.x = f[(4 * j + 0) * HW + p];
        v.y = f[(4 * j + 1) * HW + p];
        v.z = f[(4 * j + 2) * HW + p];
        v.w = f[(4 * j + 3) * HW + p];
        g_ft4[p * 4 + j] = v;
    }

    const float md0 = md[p];
    const float md1 = md[HW + p];
    const float md2 = md[2 * HW + p];
    const float d0  = dis[p];
    const float rs  = res[p];

    float ss, cs;
    sincosf((md0 - 0.5f) * 6.2831853071795864f, &ss, &cs);
    const float yst = tanf(md1 * 1.5707963267948966f);
    const float yed = tanf(-md2 * 1.5707963267948966f);
    const float ax = cs - ss * yst, ay = ss + cs * yst;
    const float bx = cs - ss * yed, by = ss + cs * yed;
    const float fx = (float)xi, fy = (float)yi;

#pragma unroll
    for (int r = 0; r < 5; r++) {
        float dval = fminf(fmaxf(d0 + rs * (float)(r - 2), 0.0f), 1.0f);
        const float ds = dval * 5.0f;
        float4 g;
        g.x = fminf(fmaxf(ax * ds + fx, 0.0f), 127.0f);
        g.y = fminf(fmaxf(ay * ds + fy, 0.0f), 127.0f);
        g.z = fminf(fmaxf(bx * ds + fx, 0.0f), 127.0f);
        g.w = fminf(fmaxf(by * ds + fy, 0.0f), 127.0f);
        g_geom[r * HW + p] = g;
    }

    float a = jloc[p];
    float m = -INFINITY;
#pragma unroll
    for (int dy = -1; dy <= 1; dy++) {
#pragma unroll
        for (int dx = -1; dx <= 1; dx++) {
            int yy = yi + dy, xx = xi + dx;
            if (yy >= 0 && yy < HH && xx >= 0 && xx < WW)
                m = fmaxf(m, jloc[yy * WW + xx]);
        }
    }
    if (a == m && a > 0.0f) {
        int pos = atomicAdd(&s_cnt, 1);
        g_keys[blockIdx.x * SEGSZ + pos] =
            ((unsigned long long)__float_as_uint(a) << 32) |
            (unsigned long long)(0xFFFFFFFFu - (unsigned)p);
    }
    __syncthreads();
    if (tid == 0) g_bcnt[blockIdx.x] = s_cnt;
}

// ---------------------------------------------------------------------------
// Kernel 2 (loi): warp = line. Load phase lane = (t_sub*4 + channel_group):
// 4 lanes cover one corner's 64B -> few cache lines per LDG. Register
// accumulation across 4 corners; smem transpose; coalesced streaming stores.
// ---------------------------------------------------------------------------
__global__ void __launch_bounds__(256) loi_kernel(float* __restrict__ out)
{
    __shared__ uint4  s_off[8][32];     // per-t corner byte offsets
    __shared__ float4 s_w[8][32];       // per-t corner weights
    __shared__ float4 s_res[8][160];    // per-t results, stride 5 (bank-pad)

    const int warp = threadIdx.x >> 5;
    const int lane = threadIdx.x & 31;
    const int l = blockIdx.x * 8 + warp;

    const float4 g = g_geom[l];   // broadcast LDG.128

    // ---- pre-phase: lane = t ----
    {
        const float t = (float)lane * (1.0f / 31.0f);
        const float omt = 1.0f - t;
        const float px = g.x * t + g.z * omt - 0.5f;
        const float py = g.y * t + g.w * omt - 0.5f;

        const float px0 = fminf(fmaxf(floorf(px), 0.0f), 127.0f);
        const float py0 = fminf(fmaxf(floorf(py), 0.0f), 127.0f);
        const float px1 = fminf(px0 + 1.0f, 127.0f);
        const float py1 = fminf(py0 + 1.0f, 127.0f);

        const int ix0 = (int)px0, iy0 = (int)py0;
        const int ix1 = (int)px1, iy1 = (int)py1;

        uint4 off;
        off.x = (unsigned)((iy0 * WW + ix0) * 64);
        off.y = (unsigned)((iy1 * WW + ix0) * 64);
        off.z = (unsigned)((iy0 * WW + ix1) * 64);
        off.w = (unsigned)((iy1 * WW + ix1) * 64);
        float4 wv;
        wv.x = (py1 - py) * (px1 - px);   // 00
        wv.y = (py - py0) * (px1 - px);   // 10
        wv.z = (py1 - py) * (px - px0);   // 01
        wv.w = (py - py0) * (px - px0);   // 11
        s_off[warp][lane] = off;
        s_w[warp][lane] = wv;
    }
    __syncwarp();

    // ---- gather phase: lane = ts*4 + cg ----
    const int ts = lane >> 2;
    const int cg = lane & 3;
    const char* fbase = (const char*)g_ft4 + cg * 16;

#pragma unroll
    for (int tg = 0; tg < 4; tg++) {
        const int tt = tg * 8 + ts;
        const uint4 o = s_off[warp][tt];
        const float4 w = s_w[warp][tt];

        ulonglong2 v0 = *(const ulonglong2*)(fbase + o.x);
        ulonglong2 v1 = *(const ulonglong2*)(fbase + o.y);
        ulonglong2 v2 = *(const ulonglong2*)(fbase + o.z);
        ulonglong2 v3 = *(const ulonglong2*)(fbase + o.w);

        unsigned long long w0 = pk2(w.x, w.x);
        unsigned long long w1 = pk2(w.y, w.y);
        unsigned long long w2 = pk2(w.z, w.z);
        unsigned long long w3 = pk2(w.w, w.w);

        unsigned long long a01 = mul2(v0.x, w0);
        unsigned long long a23 = mul2(v0.y, w0);
        a01 = fma2(v1.x, w1, a01);  a23 = fma2(v1.y, w1, a23);
        a01 = fma2(v2.x, w2, a01);  a23 = fma2(v2.y, w2, a23);
        a01 = fma2(v3.x, w3, a01);  a23 = fma2(v3.y, w3, a23);

        float2 lo = up2(a01), hi = up2(a23);
        s_res[warp][tt * 5 + cg] = make_float4(lo.x, lo.y, hi.x, hi.y);
    }
    __syncwarp();

    // ---- store phase: lane = t, coalesced streaming stores ----
    float* __restrict__ o = out + (size_t)l * (CC * NPTS) + lane;
#pragma unroll
    for (int j = 0; j < 4; j++) {
        float4 r = s_res[warp][lane * 5 + j];
        __stcs(o + (4 * j + 0) * NPTS, r.x);
        __stcs(o + (4 * j + 1) * NPTS, r.y);
        __stcs(o + (4 * j + 2) * NPTS, r.z);
        __stcs(o + (4 * j + 3) * NPTS, r.w);
    }
}

// ---------------------------------------------------------------------------
// Kernel 3 (topk): compact segments -> shared, rank-by-counting, direct emit.
// ---------------------------------------------------------------------------
__global__ void __launch_bounds__(256) topk_kernel(
    const float* __restrict__ joff, float* __restrict__ out)
{
    __shared__ alignas(16) unsigned long long s[MAXCAND + 4];
    __shared__ int s_bc[NSEG];
    __shared__ int s_ps[NSEG + 1];
    const int tid = threadIdx.x;

    for (int i = tid; i < NSEG; i += 256) s_bc[i] = g_bcnt[i];
    __syncthreads();
    if (tid == 0) {
        int acc = 0;
#pragma unroll
        for (int b = 0; b < NSEG; b++) { s_ps[b] = acc; acc += s_bc[b]; }
        s_ps[NSEG] = acc;
    }
    __syncthreads();

    int cnt = s_ps[NSEG];
    if (cnt > MAXCAND) cnt = MAXCAND;
    const int cnt_pad = (cnt + 3) & ~3;

#pragma unroll 1
    for (int b = 0; b < NSEG; b++) {
        int bc = s_bc[b];
        int dst = s_ps[b] + tid;
        if (tid < bc && dst < MAXCAND)
            s[dst] = g_keys[b * SEGSZ + tid];
    }
    if (tid < 4) s[cnt + tid] = 0ULL;
    __syncthreads();

    const int gid = blockIdx.x * 256 + tid;
    if (gid >= cnt) return;
    const unsigned long long mykey = s[gid];

    const ulonglong2* sp = (const ulonglong2*)s;
    int rank = 0;
#pragma unroll 4
    for (int i = 0; i < cnt_pad / 2; i++) {
        ulonglong2 v = sp[i];
        rank += (v.x > mykey) + (v.y > mykey);
    }

    if (rank < TOPK) {
        unsigned idx = 0xFFFFFFFFu - (unsigned)(mykey & 0xFFFFFFFFull);
        float val = __uint_as_float((unsigned)(mykey >> 32));
        float fy = (float)(idx >> 7);
        float fx = (float)(idx & 127);
        out[J_OFF + 2 * rank + 0] = fx + joff[idx] + 0.5f;
        out[J_OFF + 2 * rank + 1] = fy + joff[HW + idx] + 0.5f;
        out[S_OFF + rank] = val;
    }
}

// ---------------------------------------------------------------------------
extern "C" void kernel_launch(void* const* d_in, const int* in_sizes, int n_in,
                              void* d_out, int out_size) {
    const float* md   = (const float*)d_in[0];
    const float* dis  = (const float*)d_in[1];
    const float* res  = (const float*)d_in[2];
    const float* feat = (const float*)d_in[3];
    const float* jloc = (const float*)d_in[4];
    const float* joff = (const float*)d_in[5];
    float* out = (float*)d_out;

    prep_kernel<<<NSEG, 128>>>(feat, md, dis, res, jloc);
    loi_kernel<<<NLINES / 8, 256>>>(out);
    topk_kernel<<<16, 256>>>(joff, out);
}

// round 6
// speedup vs baseline: 1.1778x; 1.1778x over previous
#include <cuda_runtime.h>
#include <cstdint>
#include <math.h>

#define HH 128
#define WW 128
#define HW 16384
#define CC 16
#define NPTS 32
#define NLINES (5 * HW)
#define LOI_FLOATS (NLINES * (CC * NPTS))   // 41,943,040
#define J_OFF LOI_FLOATS
#define S_OFF (LOI_FLOATS + 600)
#define TOPK 300
#define NSEG 64
#define SEGSZ 256
#define MAXCAND 4096

// ---- device scratch ----
__device__ float4 g_ft4[HW * 4];             // features (H,W,C)
__device__ unsigned long long g_keys[NSEG * SEGSZ];
__device__ int g_bcnt[NSEG];

// ---- packed f32x2 helpers ----
__device__ __forceinline__ unsigned long long pk2(float lo, float hi) {
    unsigned long long r;
    asm("mov.b64 %0, {%1, %2};" : "=l"(r) : "f"(lo), "f"(hi));
    return r;
}
__device__ __forceinline__ unsigned long long mul2(unsigned long long a, unsigned long long b) {
    unsigned long long d;
    asm("mul.rn.f32x2 %0, %1, %2;" : "=l"(d) : "l"(a), "l"(b));
    return d;
}
__device__ __forceinline__ unsigned long long fma2(unsigned long long a, unsigned long long b,
                                                   unsigned long long c) {
    unsigned long long d;
    asm("fma.rn.f32x2 %0, %1, %2, %3;" : "=l"(d) : "l"(a), "l"(b), "l"(c));
    return d;
}
__device__ __forceinline__ float2 up2(unsigned long long v) {
    float2 r;
    asm("mov.b64 {%0, %1}, %2;" : "=f"(r.x), "=f"(r.y) : "l"(v));
    return r;
}

// ---------------------------------------------------------------------------
// Kernel 1 (prep): feature transpose (C,H,W)->(H,W,C) + 3x3 NMS compact.
// Geometry moved out (computed inline by loi).
// ---------------------------------------------------------------------------
__global__ void __launch_bounds__(256) prep_kernel(
    const float* __restrict__ f,
    const float* __restrict__ jloc)
{
    __shared__ int s_cnt;
    const int tid = threadIdx.x;
    const int p = blockIdx.x * 256 + tid;
    if (tid == 0) s_cnt = 0;
    __syncthreads();

    const int yi = p >> 7;
    const int xi = p & 127;

#pragma unroll
    for (int j = 0; j < 4; j++) {
        float4 v;
        v.x = f[(4 * j + 0) * HW + p];
        v.y = f[(4 * j + 1) * HW + p];
        v.z = f[(4 * j + 2) * HW + p];
        v.w = f[(4 * j + 3) * HW + p];
        g_ft4[p * 4 + j] = v;
    }

    float a = jloc[p];
    float m = -INFINITY;
#pragma unroll
    for (int dy = -1; dy <= 1; dy++) {
#pragma unroll
        for (int dx = -1; dx <= 1; dx++) {
            int yy = yi + dy, xx = xi + dx;
            if (yy >= 0 && yy < HH && xx >= 0 && xx < WW)
                m = fmaxf(m, jloc[yy * WW + xx]);
        }
    }
    if (a == m && a > 0.0f) {
        int pos = atomicAdd(&s_cnt, 1);
        g_keys[blockIdx.x * SEGSZ + pos] =
            ((unsigned long long)__float_as_uint(a) << 32) |
            (unsigned long long)(0xFFFFFFFFu - (unsigned)p);
    }
    __syncthreads();
    if (tid == 0) g_bcnt[blockIdx.x] = s_cnt;
}

// ---------------------------------------------------------------------------
// Kernel 2 (topk): compact segments -> shared, rank-by-counting, direct emit.
// Independent of loi (disjoint output ranges) -> launched before it.
// ---------------------------------------------------------------------------
__global__ void __launch_bounds__(256) topk_kernel(
    const float* __restrict__ joff, float* __restrict__ out)
{
    __shared__ alignas(16) unsigned long long s[MAXCAND + 4];
    __shared__ int s_bc[NSEG];
    __shared__ int s_ps[NSEG + 1];
    const int tid = threadIdx.x;

    if (tid < NSEG) s_bc[tid] = g_bcnt[tid];
    __syncthreads();
    if (tid == 0) {
        int acc = 0;
#pragma unroll
        for (int b = 0; b < NSEG; b++) { s_ps[b] = acc; acc += s_bc[b]; }
        s_ps[NSEG] = acc;
    }
    __syncthreads();

    int cnt = s_ps[NSEG];
    if (cnt > MAXCAND) cnt = MAXCAND;
    const int cnt_pad = (cnt + 3) & ~3;

#pragma unroll 1
    for (int b = 0; b < NSEG; b++) {
        int bc = s_bc[b];
        int dst = s_ps[b] + tid;
        if (tid < bc && dst < MAXCAND)
            s[dst] = g_keys[b * SEGSZ + tid];
    }
    if (tid < 4) s[cnt + tid] = 0ULL;
    __syncthreads();

    const int gid = blockIdx.x * 256 + tid;
    if (gid >= cnt) return;
    const unsigned long long mykey = s[gid];

    const ulonglong2* sp = (const ulonglong2*)s;
    int rank = 0;
#pragma unroll 4
    for (int i = 0; i < cnt_pad / 2; i++) {
        ulonglong2 v = sp[i];
        rank += (v.x > mykey) + (v.y > mykey);
    }

    if (rank < TOPK) {
        unsigned idx = 0xFFFFFFFFu - (unsigned)(mykey & 0xFFFFFFFFull);
        float val = __uint_as_float((unsigned)(mykey >> 32));
        float fy = (float)(idx >> 7);
        float fx = (float)(idx & 127);
        out[J_OFF + 2 * rank + 0] = fx + joff[idx] + 0.5f;
        out[J_OFF + 2 * rank + 1] = fy + joff[HW + idx] + 0.5f;
        out[S_OFF + rank] = val;
    }
}

// ---------------------------------------------------------------------------
// Kernel 3 (loi): warp = line, lane = t. Geometry computed inline (warp-
// uniform; hidden under gather latency). All 16 gather addresses independent
// -> high MLP (the R5 lesson: keep LDS off the address path).
// ---------------------------------------------------------------------------
__global__ void __launch_bounds__(256) loi_kernel(
    const float* __restrict__ md,    // (3,H,W)
    const float* __restrict__ dis,   // (H,W)
    const float* __restrict__ res,   // (H,W)
    float* __restrict__ out)
{
    const int warp = threadIdx.x >> 5;
    const int lane = threadIdx.x & 31;
    const int l = blockIdx.x * 8 + warp;

    const int r = l >> 14;            // residual index (HW = 16384)
    const int p = l & (HW - 1);
    const int yi = p >> 7;
    const int xi = p & 127;

    // --- inline geometry (broadcast loads; warp-uniform math) ---
    const float md0 = md[p];
    const float md1 = md[HW + p];
    const float md2 = md[2 * HW + p];
    float dval = dis[p] + res[p] * (float)(r - 2);
    dval = fminf(fmaxf(dval, 0.0f), 1.0f);

    float ss, cs;
    sincosf((md0 - 0.5f) * 6.2831853071795864f, &ss, &cs);
    const float yst = tanf(md1 * 1.5707963267948966f);
    const float yed = tanf(-md2 * 1.5707963267948966f);
    const float ds = dval * 5.0f;
    const float fx = (float)xi, fy = (float)yi;

    const float ux = fminf(fmaxf((cs - ss * yst) * ds + fx, 0.0f), 127.0f);
    const float uy = fminf(fmaxf((ss + cs * yst) * ds + fy, 0.0f), 127.0f);
    const float vx = fminf(fmaxf((cs - ss * yed) * ds + fx, 0.0f), 127.0f);
    const float vy = fminf(fmaxf((ss + cs * yed) * ds + fy, 0.0f), 127.0f);

    // --- per-lane sample ---
    const float t = (float)lane * (1.0f / 31.0f);
    const float omt = 1.0f - t;
    const float px = ux * t + vx * omt - 0.5f;
    const float py = uy * t + vy * omt - 0.5f;

    const float px0 = fminf(fmaxf(floorf(px), 0.0f), 127.0f);
    const float py0 = fminf(fmaxf(floorf(py), 0.0f), 127.0f);
    const float px1 = fminf(px0 + 1.0f, 127.0f);
    const float py1 = fminf(py0 + 1.0f, 127.0f);

    const int ix0 = (int)px0, iy0 = (int)py0;
    const int ix1 = (int)px1, iy1 = (int)py1;

    const unsigned long long w00 = pk2((py1 - py) * (px1 - px), (py1 - py) * (px1 - px));
    const unsigned long long w10 = pk2((py - py0) * (px1 - px), (py - py0) * (px1 - px));
    const unsigned long long w01 = pk2((py1 - py) * (px - px0), (py1 - py) * (px - px0));
    const unsigned long long w11 = pk2((py - py0) * (px - px0), (py - py0) * (px - px0));

    const ulonglong2* __restrict__ f00 = (const ulonglong2*)(g_ft4 + (iy0 * WW + ix0) * 4);
    const ulonglong2* __restrict__ f10 = (const ulonglong2*)(g_ft4 + (iy1 * WW + ix0) * 4);
    const ulonglong2* __restrict__ f01 = (const ulonglong2*)(g_ft4 + (iy0 * WW + ix1) * 4);
    const ulonglong2* __restrict__ f11 = (const ulonglong2*)(g_ft4 + (iy1 * WW + ix1) * 4);

    unsigned long long acc[8];
#pragma unroll
    for (int j = 0; j < 4; j++) {
        ulonglong2 a = f00[j];
        ulonglong2 b = f10[j];
        ulonglong2 c = f01[j];
        ulonglong2 d = f11[j];
        unsigned long long t0 = mul2(a.x, w00);
        t0 = fma2(b.x, w10, t0);
        t0 = fma2(c.x, w01, t0);
        acc[2 * j + 0] = fma2(d.x, w11, t0);
        unsigned long long t1 = mul2(a.y, w00);
        t1 = fma2(b.y, w10, t1);
        t1 = fma2(c.y, w01, t1);
        acc[2 * j + 1] = fma2(d.y, w11, t1);
    }

    float* __restrict__ o = out + (size_t)l * (CC * NPTS) + lane;
#pragma unroll
    for (int k = 0; k < 8; k++) {
        float2 v = up2(acc[k]);
        __stcs(o + (2 * k + 0) * NPTS, v.x);
        __stcs(o + (2 * k + 1) * NPTS, v.y);
    }
}

// ---------------------------------------------------------------------------
extern "C" void kernel_launch(void* const* d_in, const int* in_sizes, int n_in,
                              void* d_out, int out_size) {
    const float* md   = (const float*)d_in[0];
    const float* dis  = (const float*)d_in[1];
    const float* res  = (const float*)d_in[2];
    const float* feat = (const float*)d_in[3];
    const float* jloc = (const float*)d_in[4];
    const float* joff = (const float*)d_in[5];
    float* out = (float*)d_out;

    prep_kernel<<<NSEG, 256>>>(feat, jloc);
    topk_kernel<<<16, 256>>>(joff, out);
    loi_kernel<<<NLINES / 8, 256>>>(md, dis, res, out);
}

// round 7
// speedup vs baseline: 1.3213x; 1.1218x over previous
#include <cuda_runtime.h>
#include <cstdint>
#include <math.h>

#define HH 128
#define WW 128
#define HW 16384
#define CC 16
#define NPTS 32
#define NLINES (5 * HW)
#define LOI_FLOATS (NLINES * (CC * NPTS))   // 41,943,040
#define J_OFF LOI_FLOATS
#define S_OFF (LOI_FLOATS + 600)
#define TOPK 300
#define NSEG 64
#define SEGSZ 256
#define MAXCAND 4096
#define GRID 256
#define NTILES 256        // 16x16 tiles of 8x8 pixels

// ---- device scratch ----
__device__ float4 g_ft4[HW * 4];             // features (H,W,C)
__device__ float4 g_geom[NLINES];            // per-line (ux,uy,vx,vy)
__device__ unsigned long long g_keys[NSEG * SEGSZ];
__device__ int g_bcnt[NSEG];
__device__ unsigned g_bar  = 0;              // grid barrier arrivals
__device__ unsigned g_tile = 0;              // dynamic tile counter
__device__ unsigned g_done = 0;              // completion counter (self-clean)

// ---- packed f32x2 helpers ----
__device__ __forceinline__ unsigned long long pk2(float lo, float hi) {
    unsigned long long r;
    asm("mov.b64 %0, {%1, %2};" : "=l"(r) : "f"(lo), "f"(hi));
    return r;
}
__device__ __forceinline__ unsigned long long mul2(unsigned long long a, unsigned long long b) {
    unsigned long long d;
    asm("mul.rn.f32x2 %0, %1, %2;" : "=l"(d) : "l"(a), "l"(b));
    return d;
}
__device__ __forceinline__ unsigned long long fma2(unsigned long long a, unsigned long long b,
                                                   unsigned long long c) {
    unsigned long long d;
    asm("fma.rn.f32x2 %0, %1, %2, %3;" : "=l"(d) : "l"(a), "l"(b), "l"(c));
    return d;
}
__device__ __forceinline__ float2 up2(unsigned long long v) {
    float2 r;
    asm("mov.b64 {%0, %1}, %2;" : "=f"(r.x), "=f"(r.y) : "l"(v));
    return r;
}

// ---------------------------------------------------------------------------
// ONE fused persistent kernel. 256 blocks x 256 threads (<= resident capacity:
// 2 blocks/SM at 256 thr, ~34KB smem each).
// ---------------------------------------------------------------------------
__global__ void __launch_bounds__(256) hawp_kernel(
    const float* __restrict__ md,    // (3,H,W)
    const float* __restrict__ dis,   // (H,W)
    const float* __restrict__ res,   // (H,W)
    const float* __restrict__ f,     // (16,H,W)
    const float* __restrict__ jloc,  // (H,W)
    const float* __restrict__ joff,  // (2,H,W)
    float* __restrict__ out)
{
    __shared__ int s_cnt;
    __shared__ int s_tile;
    __shared__ alignas(16) unsigned long long s_keys[MAXCAND + 4];
    __shared__ int s_bc[NSEG];
    __shared__ int s_ps[NSEG + 1];

    const int tid = threadIdx.x;
    const int bid = blockIdx.x;

    // ================= Phase 1: prep (blocks 0..63) =================
    if (bid < NSEG) {
        if (tid == 0) s_cnt = 0;
        __syncthreads();

        const int p = bid * 256 + tid;
        const int yi = p >> 7;
        const int xi = p & 127;

        // transpose features (C,H,W) -> (H,W,C)
#pragma unroll
        for (int j = 0; j < 4; j++) {
            float4 v;
            v.x = f[(4 * j + 0) * HW + p];
            v.y = f[(4 * j + 1) * HW + p];
            v.z = f[(4 * j + 2) * HW + p];
            v.w = f[(4 * j + 3) * HW + p];
            g_ft4[p * 4 + j] = v;
        }

        // line geometry (exact trig, once per pixel)
        const float md0 = md[p];
        const float md1 = md[HW + p];
        const float md2 = md[2 * HW + p];
        const float d0  = dis[p];
        const float rs  = res[p];

        float ss, cs;
        sincosf((md0 - 0.5f) * 6.2831853071795864f, &ss, &cs);
        const float yst = tanf(md1 * 1.5707963267948966f);
        const float yed = tanf(-md2 * 1.5707963267948966f);
        const float ax = cs - ss * yst, ay = ss + cs * yst;
        const float bx = cs - ss * yed, by = ss + cs * yed;
        const float fx = (float)xi, fy = (float)yi;

#pragma unroll
        for (int r = 0; r < 5; r++) {
            float dval = fminf(fmaxf(d0 + rs * (float)(r - 2), 0.0f), 1.0f);
            const float ds = dval * 5.0f;
            float4 g;
            g.x = fminf(fmaxf(ax * ds + fx, 0.0f), 127.0f);
            g.y = fminf(fmaxf(ay * ds + fy, 0.0f), 127.0f);
            g.z = fminf(fmaxf(bx * ds + fx, 0.0f), 127.0f);
            g.w = fminf(fmaxf(by * ds + fy, 0.0f), 127.0f);
            g_geom[r * HW + p] = g;
        }

        // 3x3 NMS, per-block compaction
        float a = jloc[p];
        float m = -INFINITY;
#pragma unroll
        for (int dy = -1; dy <= 1; dy++) {
#pragma unroll
            for (int dx = -1; dx <= 1; dx++) {
                int yy = yi + dy, xx = xi + dx;
                if (yy >= 0 && yy < HH && xx >= 0 && xx < WW)
                    m = fmaxf(m, jloc[yy * WW + xx]);
            }
        }
        if (a == m && a > 0.0f) {
            int pos = atomicAdd(&s_cnt, 1);
            g_keys[bid * SEGSZ + pos] =
                ((unsigned long long)__float_as_uint(a) << 32) |
                (unsigned long long)(0xFFFFFFFFu - (unsigned)p);
        }
        __syncthreads();
        if (tid == 0) g_bcnt[bid] = s_cnt;
    }

    // ================= grid barrier (self-cleaning across replays) ==========
    __threadfence();
    __syncthreads();
    if (tid == 0) {
        atomicAdd(&g_bar, 1u);
        while (atomicAdd(&g_bar, 0u) < GRID) { }
    }
    __syncthreads();
    __threadfence();   // acquire: flush L1 so we see other SMs' prep writes

    // ================= Phase 2a: topk (blocks 0..15) =================
    if (bid < 16) {
        if (tid < NSEG) s_bc[tid] = g_bcnt[tid];
        __syncthreads();
        if (tid == 0) {
            int acc = 0;
#pragma unroll
            for (int b = 0; b < NSEG; b++) { s_ps[b] = acc; acc += s_bc[b]; }
            s_ps[NSEG] = acc;
        }
        __syncthreads();

        int cnt = s_ps[NSEG];
        if (cnt > MAXCAND) cnt = MAXCAND;
        const int cnt_pad = (cnt + 3) & ~3;

#pragma unroll 1
        for (int b = 0; b < NSEG; b++) {
            int bc = s_bc[b];
            int dst = s_ps[b] + tid;
            if (tid < bc && dst < MAXCAND)
                s_keys[dst] = g_keys[b * SEGSZ + tid];
        }
        if (tid < 4) s_keys[cnt + tid] = 0ULL;
        __syncthreads();

        const int gid = bid * 256 + tid;
        if (gid < cnt) {
            const unsigned long long mykey = s_keys[gid];
            const ulonglong2* sp = (const ulonglong2*)s_keys;
            int rank = 0;
#pragma unroll 4
            for (int i = 0; i < cnt_pad / 2; i++) {
                ulonglong2 v = sp[i];
                rank += (v.x > mykey) + (v.y > mykey);
            }
            if (rank < TOPK) {
                unsigned idx = 0xFFFFFFFFu - (unsigned)(mykey & 0xFFFFFFFFull);
                float val = __uint_as_float((unsigned)(mykey >> 32));
                float fy = (float)(idx >> 7);
                float fx = (float)(idx & 127);
                out[J_OFF + 2 * rank + 0] = fx + joff[idx] + 0.5f;
                out[J_OFF + 2 * rank + 1] = fy + joff[HW + idx] + 0.5f;
                out[S_OFF + rank] = val;
            }
        }
        __syncthreads();
    }

    // ================= Phase 2b: loi over dynamically-stolen 8x8 tiles ======
    const int warp = tid >> 5;
    const int lane = tid & 31;
    const float t   = (float)lane * (1.0f / 31.0f);
    const float omt = 1.0f - t;

    for (;;) {
        __syncthreads();
        if (tid == 0) s_tile = (int)atomicAdd(&g_tile, 1u);
        __syncthreads();
        const int tile = s_tile;
        if (tile >= NTILES) break;
        const int tx = tile & 15;
        const int ty = tile >> 4;

#pragma unroll 1
        for (int it = 0; it < 40; it++) {
            const int i = it * 8 + warp;          // 0..319
            const int pix = i / 5;
            const int r = i - pix * 5;
            const int py_t = pix >> 3;
            const int px_t = pix & 7;
            const int p = ((ty * 8 + py_t) << 7) + tx * 8 + px_t;
            const int l = r * HW + p;

            const float4 g = g_geom[l];           // broadcast

            const float px = g.x * t + g.z * omt - 0.5f;
            const float py = g.y * t + g.w * omt - 0.5f;

            const float px0 = fminf(fmaxf(floorf(px), 0.0f), 127.0f);
            const float py0 = fminf(fmaxf(floorf(py), 0.0f), 127.0f);
            const float px1 = fminf(px0 + 1.0f, 127.0f);
            const float py1 = fminf(py0 + 1.0f, 127.0f);

            const int ix0 = (int)px0, iy0 = (int)py0;
            const int ix1 = (int)px1, iy1 = (int)py1;

            const unsigned long long w00 = pk2((py1 - py) * (px1 - px), (py1 - py) * (px1 - px));
            const unsigned long long w10 = pk2((py - py0) * (px1 - px), (py - py0) * (px1 - px));
            const unsigned long long w01 = pk2((py1 - py) * (px - px0), (py1 - py) * (px - px0));
            const unsigned long long w11 = pk2((py - py0) * (px - px0), (py - py0) * (px - px0));

            const ulonglong2* __restrict__ f00 = (const ulonglong2*)(g_ft4 + (iy0 * WW + ix0) * 4);
            const ulonglong2* __restrict__ f10 = (const ulonglong2*)(g_ft4 + (iy1 * WW + ix0) * 4);
            const ulonglong2* __restrict__ f01 = (const ulonglong2*)(g_ft4 + (iy0 * WW + ix1) * 4);
            const ulonglong2* __restrict__ f11 = (const ulonglong2*)(g_ft4 + (iy1 * WW + ix1) * 4);

            unsigned long long acc[8];
#pragma unroll
            for (int j = 0; j < 4; j++) {
                ulonglong2 a = f00[j];
                ulonglong2 b = f10[j];
                ulonglong2 c = f01[j];
                ulonglong2 d = f11[j];
                unsigned long long t0 = mul2(a.x, w00);
                t0 = fma2(b.x, w10, t0);
                t0 = fma2(c.x, w01, t0);
                acc[2 * j + 0] = fma2(d.x, w11, t0);
                unsigned long long t1 = mul2(a.y, w00);
                t1 = fma2(b.y, w10, t1);
                t1 = fma2(c.y, w01, t1);
                acc[2 * j + 1] = fma2(d.y, w11, t1);
            }

            float* __restrict__ o = out + (size_t)l * (CC * NPTS) + lane;
#pragma unroll
            for (int k = 0; k < 8; k++) {
                float2 v = up2(acc[k]);
                __stcs(o + (2 * k + 0) * NPTS, v.x);
                __stcs(o + (2 * k + 1) * NPTS, v.y);
            }
        }
    }

    // ================= epilogue: last block resets counters ================
    __syncthreads();
    if (tid == 0) {
        unsigned ticket = atomicAdd(&g_done, 1u);
        if (ticket == GRID - 1) {
            g_bar = 0;
            g_tile = 0;
            g_done = 0;
            __threadfence();
        }
    }
}

// ---------------------------------------------------------------------------
extern "C" void kernel_launch(void* const* d_in, const int* in_sizes, int n_in,
                              void* d_out, int out_size) {
    const float* md   = (const float*)d_in[0];
    const float* dis  = (const float*)d_in[1];
    const float* res  = (const float*)d_in[2];
    const float* feat = (const float*)d_in[3];
    const float* jloc = (const float*)d_in[4];
    const float* joff = (const float*)d_in[5];
    float* out = (float*)d_out;

    hawp_kernel<<<GRID, 256>>>(md, dis, res, feat, jloc, joff, out);
}